// round 4
// baseline (speedup 1.0000x reference)
#include <cuda_runtime.h>
#include <cstdint>

// Problem constants (B=8, S=8192, IN=OUT=1024)
#define TOKENS 65536
#define KDIM   1024
#define NDIM   1024

// GEMM tiling: CTA 128x256, 8 warps (2m x 4n), warp tile 64x64, mma m16n8k8 tf32
#define BM 128
#define BN 256
#define BK 32
#define PAD 36                      // row stride (floats); 144B, 16B-aligned, conflict-free frags
#define NKITER (KDIM / BK)          // 32
#define A_STRIDE (BM * PAD)         // floats per A stage = 4608
#define B_STRIDE (BN * PAD)         // floats per B stage = 9216

// ---------------------------------------------------------------------------
// Device scratch
// ---------------------------------------------------------------------------
__device__ int g_cnt[2];
__device__ int g_mask_is_i32;
__device__ int g_vis[TOKENS];
__device__ int g_txt[TOKENS];

__global__ void init_kernel(const uint32_t* __restrict__ mask32) {
    if (threadIdx.x == 0) {
        int is_i32 = 1;
        #pragma unroll 8
        for (int i = 0; i < 64; i++)
            if (mask32[i] > 1u) { is_i32 = 0; break; }
        g_mask_is_i32 = is_i32;
        g_cnt[0] = 0;
        g_cnt[1] = 0;
    }
}

__global__ void build_lists_kernel(const void* __restrict__ mask) {
    int i = blockIdx.x * blockDim.x + threadIdx.x;
    if (i < TOKENS) {
        int m = g_mask_is_i32 ? ((const int*)mask)[i]
                              : (int)((const unsigned char*)mask)[i];
        if (m) { int p = atomicAdd(&g_cnt[0], 1); g_vis[p] = i; }
        else   { int p = atomicAdd(&g_cnt[1], 1); g_txt[p] = i; }
    }
}

// ---------------------------------------------------------------------------
// Helpers
// ---------------------------------------------------------------------------
__device__ __forceinline__ uint32_t f2tf32(float f) {
    uint32_t u;
    asm("cvt.rna.tf32.f32 %0, %1;" : "=r"(u) : "f"(f));
    return u;
}

__device__ __forceinline__ void cp_async16(uint32_t d, const void* s) {
    asm volatile("cp.async.cg.shared.global [%0], [%1], 16;" :: "r"(d), "l"(s));
}
#define CP_COMMIT() asm volatile("cp.async.commit_group;")

// ---------------------------------------------------------------------------
// Routed GEMM
//   grid = (NDIM/BN = 4, 513); 256 threads
//   double-buffered cp.async; per-stage in-place tf32 convert pass
// ---------------------------------------------------------------------------
__global__ void __launch_bounds__(256, 1) routed_gemm_kernel(
    const float* __restrict__ x,
    const float* __restrict__ w_v,
    const float* __restrict__ w_t,
    float* __restrict__ out)
{
    extern __shared__ float smem[];
    float* As = smem;                      // [2][BM][PAD]
    float* Bs = smem + 2 * A_STRIDE;       // [2][BN][PAD]
    __shared__ int rows_s[BM];

    const int cv = g_cnt[0];
    const int ct = g_cnt[1];
    const int vis_tiles = (cv + BM - 1) >> 7;

    const int tile = blockIdx.y;
    const int* list;
    const float* W;
    int base, count;
    if (tile < vis_tiles) {
        list = g_vis; W = w_v; base = tile << 7; count = cv;
    } else {
        base = (tile - vis_tiles) << 7;
        count = ct;
        if (base >= count) return;
        list = g_txt; W = w_t;
    }
    const int mvalid = min(BM, count - base);

    const int tid = threadIdx.x;
    if (tid < BM) rows_s[tid] = (tid < mvalid) ? list[base + tid] : list[base];
    __syncthreads();

    const int n_cta = blockIdx.x * BN;

    // ---- async stage loader: A (128 rows) + B (256 rows), 128B per row
    auto load_stage = [&](int kt, int s) {
        const int k0 = kt * BK;
        float* Ab = As + s * A_STRIDE;
        float* Bb = Bs + s * B_STRIDE;
        #pragma unroll
        for (int i = 0; i < 4; i++) {                 // A: 1024 float4
            const int idx = i * 256 + tid;
            const int r = idx >> 3, cg = idx & 7;
            uint32_t d = (uint32_t)__cvta_generic_to_shared(&Ab[r * PAD + cg * 4]);
            cp_async16(d, x + (size_t)rows_s[r] * KDIM + k0 + cg * 4);
        }
        #pragma unroll
        for (int i = 0; i < 8; i++) {                 // B: 2048 float4
            const int idx = i * 256 + tid;
            const int r = idx >> 3, cg = idx & 7;
            uint32_t d = (uint32_t)__cvta_generic_to_shared(&Bb[r * PAD + cg * 4]);
            cp_async16(d, W + (size_t)(n_cta + r) * KDIM + k0 + cg * 4);
        }
        CP_COMMIT();
    };

    // ---- in-place tf32 (rna) convert of one stage: 3072 float4, 12/thread
    auto convert_stage = [&](int s) {
        uint4* Ab = (uint4*)(As + s * A_STRIDE);      // via padded rows
        float* Abf = As + s * A_STRIDE;
        float* Bbf = Bs + s * B_STRIDE;
        #pragma unroll
        for (int i = 0; i < 4; i++) {
            const int idx = i * 256 + tid;
            const int r = idx >> 3, cg = idx & 7;
            uint4* p = (uint4*)&Abf[r * PAD + cg * 4];
            uint4 v = *p;
            v.x = f2tf32(__uint_as_float(v.x));
            v.y = f2tf32(__uint_as_float(v.y));
            v.z = f2tf32(__uint_as_float(v.z));
            v.w = f2tf32(__uint_as_float(v.w));
            *p = v;
        }
        #pragma unroll
        for (int i = 0; i < 8; i++) {
            const int idx = i * 256 + tid;
            const int r = idx >> 3, cg = idx & 7;
            uint4* p = (uint4*)&Bbf[r * PAD + cg * 4];
            uint4 v = *p;
            v.x = f2tf32(__uint_as_float(v.x));
            v.y = f2tf32(__uint_as_float(v.y));
            v.z = f2tf32(__uint_as_float(v.z));
            v.w = f2tf32(__uint_as_float(v.w));
            *p = v;
        }
        (void)Ab;
    };

    const int lane = tid & 31;
    const int g  = lane >> 2;          // 0..7
    const int tg = lane & 3;           // 0..3
    const int wid = tid >> 5;
    const int m0  = (wid >> 2) * 64;   // 2 warps in m
    const int n0w = (wid & 3) * 64;    // 4 warps in n

    float acc[4][8][4];
    #pragma unroll
    for (int mt = 0; mt < 4; mt++)
        #pragma unroll
        for (int nt = 0; nt < 8; nt++)
            #pragma unroll
            for (int r = 0; r < 4; r++) acc[mt][nt][r] = 0.0f;

    load_stage(0, 0);
    load_stage(1, 1);

    for (int kt = 0; kt < NKITER; kt++) {
        const int s = kt & 1;
        if (kt + 1 < NKITER) asm volatile("cp.async.wait_group 1;");
        else                 asm volatile("cp.async.wait_group 0;");
        __syncthreads();               // stage s loaded; prior readers of s done

        convert_stage(s);
        __syncthreads();               // converted data visible to all warps

        const uint32_t* Ab = (const uint32_t*)(As + s * A_STRIDE);
        const uint32_t* Bb = (const uint32_t*)(Bs + s * B_STRIDE);

        #pragma unroll
        for (int ks = 0; ks < 4; ks++) {
            const int c = ks * 8 + tg;
            uint32_t a[4][4], b[8][2];
            #pragma unroll
            for (int mt = 0; mt < 4; mt++) {
                const int r = m0 + mt * 16 + g;
                a[mt][0] = Ab[r * PAD + c];
                a[mt][1] = Ab[(r + 8) * PAD + c];
                a[mt][2] = Ab[r * PAD + c + 4];
                a[mt][3] = Ab[(r + 8) * PAD + c + 4];
            }
            #pragma unroll
            for (int nt = 0; nt < 8; nt++) {
                const int n = n0w + nt * 8 + g;
                b[nt][0] = Bb[n * PAD + c];
                b[nt][1] = Bb[n * PAD + c + 4];
            }
            #pragma unroll
            for (int mt = 0; mt < 4; mt++)
                #pragma unroll
                for (int nt = 0; nt < 8; nt++)
                    asm volatile(
                        "mma.sync.aligned.m16n8k8.row.col.f32.tf32.tf32.f32 "
                        "{%0,%1,%2,%3}, {%4,%5,%6,%7}, {%8,%9}, {%0,%1,%2,%3};\n"
                        : "+f"(acc[mt][nt][0]), "+f"(acc[mt][nt][1]),
                          "+f"(acc[mt][nt][2]), "+f"(acc[mt][nt][3])
                        : "r"(a[mt][0]), "r"(a[mt][1]),
                          "r"(a[mt][2]), "r"(a[mt][3]),
                          "r"(b[nt][0]), "r"(b[nt][1]));
        }

        __syncthreads();               // all MMA reads of stage s done
        if (kt + 2 < NKITER) load_stage(kt + 2, s);
    }

    // ---- epilogue: scatter float2 per fragment row
    #pragma unroll
    for (int mt = 0; mt < 4; mt++) {
        const int r_lo = m0 + mt * 16 + g;
        const int r_hi = r_lo + 8;
        const bool ok_lo = r_lo < mvalid;
        const bool ok_hi = r_hi < mvalid;
        float* row_lo = ok_lo ? out + (size_t)rows_s[r_lo] * NDIM + n_cta : nullptr;
        float* row_hi = ok_hi ? out + (size_t)rows_s[r_hi] * NDIM + n_cta : nullptr;
        #pragma unroll
        for (int nt = 0; nt < 8; nt++) {
            const int col = n0w + nt * 8 + tg * 2;
            if (ok_lo)
                *(float2*)(row_lo + col) = make_float2(acc[mt][nt][0], acc[mt][nt][1]);
            if (ok_hi)
                *(float2*)(row_hi + col) = make_float2(acc[mt][nt][2], acc[mt][nt][3]);
        }
    }
}

// ---------------------------------------------------------------------------
// Launch (graph-capturable)
// ---------------------------------------------------------------------------
extern "C" void kernel_launch(void* const* d_in, const int* in_sizes, int n_in,
                              void* d_out, int out_size)
{
    const float* x    = (const float*)d_in[0];
    const void*  mask = d_in[1];
    const float* w_v  = (const float*)d_in[2];
    const float* w_t  = (const float*)d_in[3];
    float*       out  = (float*)d_out;

    init_kernel<<<1, 32>>>((const uint32_t*)mask);
    build_lists_kernel<<<TOKENS / 256, 256>>>(mask);

    const size_t smem_bytes = (size_t)2 * (A_STRIDE + B_STRIDE) * sizeof(float); // 110592
    cudaFuncSetAttribute(routed_gemm_kernel,
                         cudaFuncAttributeMaxDynamicSharedMemorySize,
                         (int)smem_bytes);

    dim3 grid(NDIM / BN, 513);
    routed_gemm_kernel<<<grid, 256, smem_bytes>>>(x, w_v, w_t, out);
}

// round 5
// speedup vs baseline: 1.3639x; 1.3639x over previous
#include <cuda_runtime.h>
#include <cstdint>

// Problem constants (B=8, S=8192, IN=OUT=1024)
#define TOKENS 65536
#define KDIM   1024
#define NDIM   1024

// GEMM tiling: CTA 128x128, 8 warps (2m x 4n), warp tile 64x32, mma m16n8k8 tf32
#define BM 128
#define BN 128
#define BK 32
#define PAD 40                       // floats per smem row; (8g+2tg) mod 32 covers all banks
#define NKITER (KDIM / BK)           // 32
#define A_STRIDE (BM * PAD)          // 5120 floats per stage
#define B_STRIDE (BN * PAD)          // 5120 floats per stage

// ---------------------------------------------------------------------------
// Device scratch (static: allocation-free)
// ---------------------------------------------------------------------------
__device__ int g_cnt[2];
__device__ int g_mask_is_i32;
__device__ int g_list[TOKENS];          // token ids in routed order is implicit via g_dst
__device__ int g_rows[TOKENS];          // compacted row -> token id (for epilogue scatter)
__device__ int g_dst[TOKENS];           // token id -> compacted row
// x gathered into routed order, tf32-rounded, k-permuted. +128 pad rows for tile overrun.
__device__ float g_xg[(TOKENS + 128) * KDIM];
// weights tf32-rounded, k-permuted: [0]=w_v, [1]=w_t
__device__ float g_wc[2 * NDIM * KDIM];

__global__ void init_kernel(const uint32_t* __restrict__ mask32) {
    if (threadIdx.x == 0) {
        int is_i32 = 1;
        #pragma unroll 8
        for (int i = 0; i < 64; i++)
            if (mask32[i] > 1u) { is_i32 = 0; break; }
        g_mask_is_i32 = is_i32;
        g_cnt[0] = 0;
        g_cnt[1] = 0;
    }
}

__global__ void build_lists_kernel(const void* __restrict__ mask) {
    int i = blockIdx.x * blockDim.x + threadIdx.x;
    if (i < TOKENS) {
        int m = g_mask_is_i32 ? ((const int*)mask)[i]
                              : (int)((const unsigned char*)mask)[i];
        if (m) { int p = atomicAdd(&g_cnt[0], 1); g_dst[i] = p; }        // vis: rows [0, cv)
        else   { int p = atomicAdd(&g_cnt[1], 1); g_dst[i] = ~p; }       // txt: rows [cv, ...)
    }
}

__device__ __forceinline__ uint32_t f2tf32(float f) {
    uint32_t u;
    asm("cvt.rna.tf32.f32 %0, %1;" : "=r"(u) : "f"(f));
    return u;
}

// permute 8 floats [s0..s7] -> [s0,s4,s1,s5,s2,s6,s3,s7], rounded to tf32
__device__ __forceinline__ void round_permute8(const float4 v0, const float4 v1,
                                               float4& o0, float4& o1) {
    o0.x = __uint_as_float(f2tf32(v0.x)); o0.y = __uint_as_float(f2tf32(v1.x));
    o0.z = __uint_as_float(f2tf32(v0.y)); o0.w = __uint_as_float(f2tf32(v1.y));
    o1.x = __uint_as_float(f2tf32(v0.z)); o1.y = __uint_as_float(f2tf32(v1.z));
    o1.z = __uint_as_float(f2tf32(v0.w)); o1.w = __uint_as_float(f2tf32(v1.w));
}

// One block per token row: gather into routed position, round, permute.
__global__ void __launch_bounds__(128) prep_x_kernel(const float* __restrict__ x) {
    const int tok = blockIdx.x;
    const int t = threadIdx.x;                 // 128 threads x 8 floats = 1024
    const int cv = g_cnt[0];
    int d = g_dst[tok];
    const int row = (d >= 0) ? d : cv + ~d;
    if (t == 0) g_rows[row] = tok;
    const float4* src = (const float4*)(x + (size_t)tok * KDIM + t * 8);
    float4* dst = (float4*)(g_xg + (size_t)row * KDIM + t * 8);
    float4 o0, o1;
    round_permute8(src[0], src[1], o0, o1);
    dst[0] = o0; dst[1] = o1;
}

// One block per weight row (2048 rows: w_v then w_t).
__global__ void __launch_bounds__(128) prep_w_kernel(const float* __restrict__ w_v,
                                                     const float* __restrict__ w_t) {
    const int r = blockIdx.x;                  // 0..2047
    const int t = threadIdx.x;
    const float* src_base = (r < NDIM) ? w_v : w_t;
    const int rr = (r < NDIM) ? r : r - NDIM;
    const float4* src = (const float4*)(src_base + (size_t)rr * KDIM + t * 8);
    float4* dst = (float4*)(g_wc + (size_t)r * KDIM + t * 8);
    float4 o0, o1;
    round_permute8(src[0], src[1], o0, o1);
    dst[0] = o0; dst[1] = o1;
}

__device__ __forceinline__ void cp_async16(uint32_t d, const void* s) {
    asm volatile("cp.async.cg.shared.global [%0], [%1], 16;" :: "r"(d), "l"(s));
}
#define CP_COMMIT() asm volatile("cp.async.commit_group;")

// ---------------------------------------------------------------------------
// Routed GEMM: A from g_xg (contiguous routed rows), B from g_wc.
//   grid = (NDIM/BN = 8, 513); 256 threads, occ 2.
// ---------------------------------------------------------------------------
__global__ void __launch_bounds__(256, 2) routed_gemm_kernel(float* __restrict__ out)
{
    extern __shared__ float smem[];
    float* As = smem;                      // [2][BM][PAD]
    float* Bs = smem + 2 * A_STRIDE;       // [2][BN][PAD]
    __shared__ int rows_s[BM];

    const int cv = g_cnt[0];
    const int ct = g_cnt[1];
    const int vis_tiles = (cv + BM - 1) >> 7;

    const int tile = blockIdx.y;
    int row0, count_lim;
    const float* W;
    if (tile < vis_tiles) {
        row0 = tile << 7;           count_lim = cv;            W = g_wc;
    } else {
        const int base = (tile - vis_tiles) << 7;
        if (base >= ct) return;
        row0 = cv + base;           count_lim = cv + ct;       W = g_wc + (size_t)NDIM * KDIM;
    }
    const int mvalid = min(BM, count_lim - row0);

    const int tid = threadIdx.x;
    if (tid < BM) rows_s[tid] = g_rows[min(row0 + tid, TOKENS - 1)];
    __syncthreads();

    const int n_cta = blockIdx.x * BN;

    auto load_stage = [&](int kt, int s) {
        const int k0 = kt * BK;
        float* Ab = As + s * A_STRIDE;
        float* Bb = Bs + s * B_STRIDE;
        #pragma unroll
        for (int i = 0; i < 4; i++) {                 // A: 1024 x 16B
            const int idx = i * 256 + tid;
            const int r = idx >> 3, cg = idx & 7;
            uint32_t d = (uint32_t)__cvta_generic_to_shared(&Ab[r * PAD + cg * 4]);
            cp_async16(d, g_xg + (size_t)(row0 + r) * KDIM + k0 + cg * 4);
        }
        #pragma unroll
        for (int i = 0; i < 4; i++) {                 // B: 1024 x 16B
            const int idx = i * 256 + tid;
            const int r = idx >> 3, cg = idx & 7;
            uint32_t d = (uint32_t)__cvta_generic_to_shared(&Bb[r * PAD + cg * 4]);
            cp_async16(d, W + (size_t)(n_cta + r) * KDIM + k0 + cg * 4);
        }
        CP_COMMIT();
    };

    const int lane = tid & 31;
    const int g  = lane >> 2;          // 0..7
    const int tg = lane & 3;           // 0..3
    const int wid = tid >> 5;
    const int m0  = (wid >> 2) * 64;   // 2 warps in m
    const int n0w = (wid & 3) * 32;    // 4 warps in n

    float acc[4][4][4];
    #pragma unroll
    for (int mt = 0; mt < 4; mt++)
        #pragma unroll
        for (int nt = 0; nt < 4; nt++)
            #pragma unroll
            for (int r = 0; r < 4; r++) acc[mt][nt][r] = 0.0f;

    load_stage(0, 0);
    load_stage(1, 1);

    for (int kt = 0; kt < NKITER; kt++) {
        const int s = kt & 1;
        if (kt + 1 < NKITER) asm volatile("cp.async.wait_group 1;");
        else                 asm volatile("cp.async.wait_group 0;");
        __syncthreads();

        const float* Ab = As + s * A_STRIDE;
        const float* Bb = Bs + s * B_STRIDE;

        #pragma unroll
        for (int ks = 0; ks < 4; ks++) {
            const int c2 = ks * 8 + tg * 2;     // permuted: (c, c+4) -> adjacent pair
            float2 a[4][2], b[4];
            #pragma unroll
            for (int mt = 0; mt < 4; mt++) {
                const int r = m0 + mt * 16 + g;
                a[mt][0] = *(const float2*)&Ab[r * PAD + c2];        // (a0, a2)
                a[mt][1] = *(const float2*)&Ab[(r + 8) * PAD + c2];  // (a1, a3)
            }
            #pragma unroll
            for (int nt = 0; nt < 4; nt++) {
                const int n = n0w + nt * 8 + g;
                b[nt] = *(const float2*)&Bb[n * PAD + c2];           // (b0, b1)
            }
            #pragma unroll
            for (int mt = 0; mt < 4; mt++)
                #pragma unroll
                for (int nt = 0; nt < 4; nt++)
                    asm volatile(
                        "mma.sync.aligned.m16n8k8.row.col.f32.tf32.tf32.f32 "
                        "{%0,%1,%2,%3}, {%4,%5,%6,%7}, {%8,%9}, {%0,%1,%2,%3};\n"
                        : "+f"(acc[mt][nt][0]), "+f"(acc[mt][nt][1]),
                          "+f"(acc[mt][nt][2]), "+f"(acc[mt][nt][3])
                        : "f"(a[mt][0].x), "f"(a[mt][1].x),
                          "f"(a[mt][0].y), "f"(a[mt][1].y),
                          "f"(b[nt].x),    "f"(b[nt].y));
        }

        __syncthreads();
        if (kt + 2 < NKITER) load_stage(kt + 2, s);
    }

    // ---- epilogue: scatter float2 per fragment row
    #pragma unroll
    for (int mt = 0; mt < 4; mt++) {
        const int r_lo = m0 + mt * 16 + g;
        const int r_hi = r_lo + 8;
        const bool ok_lo = r_lo < mvalid;
        const bool ok_hi = r_hi < mvalid;
        float* row_lo = ok_lo ? out + (size_t)rows_s[r_lo] * NDIM + n_cta : nullptr;
        float* row_hi = ok_hi ? out + (size_t)rows_s[r_hi] * NDIM + n_cta : nullptr;
        #pragma unroll
        for (int nt = 0; nt < 4; nt++) {
            const int col = n0w + nt * 8 + tg * 2;
            if (ok_lo)
                *(float2*)(row_lo + col) = make_float2(acc[mt][nt][0], acc[mt][nt][1]);
            if (ok_hi)
                *(float2*)(row_hi + col) = make_float2(acc[mt][nt][2], acc[mt][nt][3]);
        }
    }
}

// ---------------------------------------------------------------------------
// Launch (graph-capturable)
// ---------------------------------------------------------------------------
extern "C" void kernel_launch(void* const* d_in, const int* in_sizes, int n_in,
                              void* d_out, int out_size)
{
    const float* x    = (const float*)d_in[0];
    const void*  mask = d_in[1];
    const float* w_v  = (const float*)d_in[2];
    const float* w_t  = (const float*)d_in[3];
    float*       out  = (float*)d_out;

    init_kernel<<<1, 32>>>((const uint32_t*)mask);
    build_lists_kernel<<<TOKENS / 256, 256>>>(mask);
    prep_x_kernel<<<TOKENS, 128>>>(x);
    prep_w_kernel<<<2 * NDIM, 128>>>(w_v, w_t);

    const size_t smem_bytes = (size_t)2 * (A_STRIDE + B_STRIDE) * sizeof(float); // 81920
    cudaFuncSetAttribute(routed_gemm_kernel,
                         cudaFuncAttributeMaxDynamicSharedMemorySize,
                         (int)smem_bytes);

    dim3 grid(NDIM / BN, 513);
    routed_gemm_kernel<<<grid, 256, smem_bytes>>>(out);
}

// round 6
// speedup vs baseline: 1.7082x; 1.2524x over previous
#include <cuda_runtime.h>
#include <cuda_fp16.h>
#include <cstdint>

// Problem constants (B=8, S=8192, IN=OUT=1024)
#define TOKENS 65536
#define KDIM   1024
#define NDIM   1024

// GEMM tiling: CTA 128x128, 8 warps (2m x 4n), warp tile 64x32, mma m16n8k16 f16
#define BM 128
#define BN 128
#define BK 32
#define PAD_H 40                     // halves per smem row (80B, 8B-aligned)
#define NKITER (KDIM / BK)           // 32
#define A_STRIDE (BM * PAD_H)        // halves per A stage
#define B_STRIDE (BN * PAD_H)        // halves per B stage

// ---------------------------------------------------------------------------
// Device scratch (static: allocation-free)
// ---------------------------------------------------------------------------
__device__ int g_cnt[2];
__device__ int g_mask_is_i32;
__device__ int g_rows[TOKENS];          // compacted row -> token id
__device__ int g_dst[TOKENS];           // token id -> compacted row (vis >=0, txt ~p)
// x gathered into routed order, fp16(rna), k-permuted. +128 pad rows.
__device__ __align__(16) __half g_xh[(size_t)(TOKENS + 128) * KDIM];
// weights fp16(rna), k-permuted: [0]=w_v, [1]=w_t
__device__ __align__(16) __half g_wh[(size_t)2 * NDIM * KDIM];

__global__ void init_kernel(const uint32_t* __restrict__ mask32) {
    if (threadIdx.x == 0) {
        int is_i32 = 1;
        #pragma unroll 8
        for (int i = 0; i < 64; i++)
            if (mask32[i] > 1u) { is_i32 = 0; break; }
        g_mask_is_i32 = is_i32;
        g_cnt[0] = 0;
        g_cnt[1] = 0;
    }
}

__global__ void build_lists_kernel(const void* __restrict__ mask) {
    int i = blockIdx.x * blockDim.x + threadIdx.x;
    if (i < TOKENS) {
        int m = g_mask_is_i32 ? ((const int*)mask)[i]
                              : (int)((const unsigned char*)mask)[i];
        if (m) { int p = atomicAdd(&g_cnt[0], 1); g_dst[i] = p; }
        else   { int p = atomicAdd(&g_cnt[1], 1); g_dst[i] = ~p; }
    }
}

// ---------------------------------------------------------------------------
// Prep: fp32 -> fp16 (rna) with k-permutation inside each 16-block:
//   out[16B + 4s + {0,1,2,3}] = in[16B + {2s, 2s+1, 2s+8, 2s+9}]
// Thread t handles 8 output halves: block B = t>>1, h = t&1, s in {2h, 2h+1}.
// Needs inputs {4h..4h+3} and {4h+8..4h+11} = two float4 loads.
// Output order: [v0.x v0.y v1.x v1.y  v0.z v0.w v1.z v1.w]
// ---------------------------------------------------------------------------
__device__ __forceinline__ void cvt_permute8(const float4 v0, const float4 v1,
                                             __half out[8]) {
    out[0] = __float2half_rn(v0.x); out[1] = __float2half_rn(v0.y);
    out[2] = __float2half_rn(v1.x); out[3] = __float2half_rn(v1.y);
    out[4] = __float2half_rn(v0.z); out[5] = __float2half_rn(v0.w);
    out[6] = __float2half_rn(v1.z); out[7] = __float2half_rn(v1.w);
}

__global__ void __launch_bounds__(128) prep_x_kernel(const float* __restrict__ x) {
    const int tok = blockIdx.x;
    const int t = threadIdx.x;                 // 128 threads
    const int cv = g_cnt[0];
    const int d = g_dst[tok];
    const int row = (d >= 0) ? d : cv + ~d;
    if (t == 0) g_rows[row] = tok;
    const int blk = t >> 1, h = t & 1;
    const float* src = x + (size_t)tok * KDIM + blk * 16;
    const float4 v0 = *(const float4*)(src + 4 * h);
    const float4 v1 = *(const float4*)(src + 4 * h + 8);
    __half o[8];
    cvt_permute8(v0, v1, o);
    *(uint4*)(g_xh + (size_t)row * KDIM + blk * 16 + 8 * h) = *(const uint4*)o;
}

__global__ void __launch_bounds__(128) prep_w_kernel(const float* __restrict__ w_v,
                                                     const float* __restrict__ w_t) {
    const int r = blockIdx.x;                  // 0..2047
    const int t = threadIdx.x;
    const float* src_base = (r < NDIM) ? w_v : w_t;
    const int rr = (r < NDIM) ? r : r - NDIM;
    const int blk = t >> 1, h = t & 1;
    const float* src = src_base + (size_t)rr * KDIM + blk * 16;
    const float4 v0 = *(const float4*)(src + 4 * h);
    const float4 v1 = *(const float4*)(src + 4 * h + 8);
    __half o[8];
    cvt_permute8(v0, v1, o);
    *(uint4*)(g_wh + (size_t)r * KDIM + blk * 16 + 8 * h) = *(const uint4*)o;
}

__device__ __forceinline__ void cp_async16(uint32_t d, const void* s) {
    asm volatile("cp.async.cg.shared.global [%0], [%1], 16;" :: "r"(d), "l"(s));
}
#define CP_COMMIT() asm volatile("cp.async.commit_group;")

// ---------------------------------------------------------------------------
// Routed GEMM (fp16 MMA): grid = (8, 513); 256 threads, occ 2.
// ---------------------------------------------------------------------------
__global__ void __launch_bounds__(256, 2) routed_gemm_kernel(float* __restrict__ out)
{
    extern __shared__ __half smem[];
    __half* As = smem;                      // [2][BM][PAD_H]
    __half* Bs = smem + 2 * A_STRIDE;       // [2][BN][PAD_H]
    __shared__ int rows_s[BM];

    const int cv = g_cnt[0];
    const int ct = g_cnt[1];
    const int vis_tiles = (cv + BM - 1) >> 7;

    const int tile = blockIdx.y;
    int row0, count_lim;
    const __half* W;
    if (tile < vis_tiles) {
        row0 = tile << 7;          count_lim = cv;       W = g_wh;
    } else {
        const int base = (tile - vis_tiles) << 7;
        if (base >= ct) return;
        row0 = cv + base;          count_lim = cv + ct;  W = g_wh + (size_t)NDIM * KDIM;
    }
    const int mvalid = min(BM, count_lim - row0);

    const int tid = threadIdx.x;
    if (tid < BM) rows_s[tid] = g_rows[min(row0 + tid, TOKENS - 1)];
    __syncthreads();

    const int n_cta = blockIdx.x * BN;

    // stage loader: 64B of k per row; 4 x 16B chunks per row; 2 iters each of A/B
    auto load_stage = [&](int kt, int s) {
        const int k0 = kt * BK;                  // in halves
        __half* Ab = As + s * A_STRIDE;
        __half* Bb = Bs + s * B_STRIDE;
        #pragma unroll
        for (int i = 0; i < 2; i++) {            // A: 512 chunks
            const int idx = i * 256 + tid;
            const int r = idx >> 2, cg = idx & 3;
            uint32_t d = (uint32_t)__cvta_generic_to_shared(&Ab[r * PAD_H + cg * 8]);
            cp_async16(d, g_xh + (size_t)(row0 + r) * KDIM + k0 + cg * 8);
        }
        #pragma unroll
        for (int i = 0; i < 2; i++) {            // B: 512 chunks
            const int idx = i * 256 + tid;
            const int r = idx >> 2, cg = idx & 3;
            uint32_t d = (uint32_t)__cvta_generic_to_shared(&Bb[r * PAD_H + cg * 8]);
            cp_async16(d, W + (size_t)(n_cta + r) * KDIM + k0 + cg * 8);
        }
        CP_COMMIT();
    };

    const int lane = tid & 31;
    const int g  = lane >> 2;          // 0..7
    const int tg = lane & 3;           // 0..3
    const int wid = tid >> 5;
    const int m0  = (wid >> 2) * 64;   // 2 warps in m
    const int n0w = (wid & 3) * 32;    // 4 warps in n

    float acc[4][4][4];
    #pragma unroll
    for (int mt = 0; mt < 4; mt++)
        #pragma unroll
        for (int nt = 0; nt < 4; nt++)
            #pragma unroll
            for (int r = 0; r < 4; r++) acc[mt][nt][r] = 0.0f;

    load_stage(0, 0);
    load_stage(1, 1);

    for (int kt = 0; kt < NKITER; kt++) {
        const int s = kt & 1;
        if (kt + 1 < NKITER) asm volatile("cp.async.wait_group 1;");
        else                 asm volatile("cp.async.wait_group 0;");
        __syncthreads();

        const __half* Ab = As + s * A_STRIDE;
        const __half* Bb = Bs + s * B_STRIDE;

        #pragma unroll
        for (int ks = 0; ks < 2; ks++) {            // 2 k16-chunks per BK=32
            const int co = ks * 16 + tg * 4;        // permuted fragment offset (halves)
            uint2 a_lo[4], a_hi[4], b[4];
            #pragma unroll
            for (int mt = 0; mt < 4; mt++) {
                const int r = m0 + mt * 16 + g;
                a_lo[mt] = *(const uint2*)&Ab[r * PAD_H + co];        // {a0a1, a2a3}
                a_hi[mt] = *(const uint2*)&Ab[(r + 8) * PAD_H + co];  // {a1-pair, a3-pair}
            }
            #pragma unroll
            for (int nt = 0; nt < 4; nt++) {
                const int n = n0w + nt * 8 + g;
                b[nt] = *(const uint2*)&Bb[n * PAD_H + co];           // {b0b1, b2b3}
            }
            #pragma unroll
            for (int mt = 0; mt < 4; mt++)
                #pragma unroll
                for (int nt = 0; nt < 4; nt++)
                    asm volatile(
                        "mma.sync.aligned.m16n8k16.row.col.f32.f16.f16.f32 "
                        "{%0,%1,%2,%3}, {%4,%5,%6,%7}, {%8,%9}, {%0,%1,%2,%3};\n"
                        : "+f"(acc[mt][nt][0]), "+f"(acc[mt][nt][1]),
                          "+f"(acc[mt][nt][2]), "+f"(acc[mt][nt][3])
                        : "r"(a_lo[mt].x), "r"(a_hi[mt].x),
                          "r"(a_lo[mt].y), "r"(a_hi[mt].y),
                          "r"(b[nt].x),    "r"(b[nt].y));
        }

        __syncthreads();
        if (kt + 2 < NKITER) load_stage(kt + 2, s);
    }

    // ---- epilogue: scatter float2 per fragment row (same D layout as tf32)
    #pragma unroll
    for (int mt = 0; mt < 4; mt++) {
        const int r_lo = m0 + mt * 16 + g;
        const int r_hi = r_lo + 8;
        const bool ok_lo = r_lo < mvalid;
        const bool ok_hi = r_hi < mvalid;
        float* row_lo = ok_lo ? out + (size_t)rows_s[r_lo] * NDIM + n_cta : nullptr;
        float* row_hi = ok_hi ? out + (size_t)rows_s[r_hi] * NDIM + n_cta : nullptr;
        #pragma unroll
        for (int nt = 0; nt < 4; nt++) {
            const int col = n0w + nt * 8 + tg * 2;
            if (ok_lo)
                *(float2*)(row_lo + col) = make_float2(acc[mt][nt][0], acc[mt][nt][1]);
            if (ok_hi)
                *(float2*)(row_hi + col) = make_float2(acc[mt][nt][2], acc[mt][nt][3]);
        }
    }
}

// ---------------------------------------------------------------------------
// Launch (graph-capturable)
// ---------------------------------------------------------------------------
extern "C" void kernel_launch(void* const* d_in, const int* in_sizes, int n_in,
                              void* d_out, int out_size)
{
    const float* x    = (const float*)d_in[0];
    const void*  mask = d_in[1];
    const float* w_v  = (const float*)d_in[2];
    const float* w_t  = (const float*)d_in[3];
    float*       out  = (float*)d_out;

    init_kernel<<<1, 32>>>((const uint32_t*)mask);
    build_lists_kernel<<<TOKENS / 256, 256>>>(mask);
    prep_x_kernel<<<TOKENS, 128>>>(x);
    prep_w_kernel<<<2 * NDIM, 128>>>(w_v, w_t);

    const size_t smem_bytes = (size_t)2 * (A_STRIDE + B_STRIDE) * sizeof(__half); // 40960
    cudaFuncSetAttribute(routed_gemm_kernel,
                         cudaFuncAttributeMaxDynamicSharedMemorySize,
                         (int)smem_bytes);

    dim3 grid(NDIM / BN, 513);
    routed_gemm_kernel<<<grid, 256, smem_bytes>>>(out);
}

// round 7
// speedup vs baseline: 1.7870x; 1.0461x over previous
#include <cuda_runtime.h>
#include <cuda_fp16.h>
#include <cstdint>

// Problem constants (B=8, S=8192, IN=OUT=1024)
#define TOKENS 65536
#define KDIM   1024
#define NDIM   1024

// GEMM tiling: CTA 128x128, 8 warps (2m x 4n), warp tile 64x32, mma m16n8k16 f16
#define BM 128
#define BN 128
#define BK 32
#define PAD_H 40                     // halves per smem row (80B)
#define NKITER (KDIM / BK)           // 32
#define STAGES 4
#define A_STRIDE (BM * PAD_H)        // halves per A stage
#define B_STRIDE (BN * PAD_H)        // halves per B stage
#define STAGE_H (A_STRIDE + B_STRIDE)

// ---------------------------------------------------------------------------
// Device scratch (static: allocation-free)
// ---------------------------------------------------------------------------
__device__ int g_cnt[2];
__device__ int g_mask_is_i32;
__device__ int g_rows[TOKENS];          // compacted row -> token id
__device__ int g_dst[TOKENS];           // token id -> compacted row (vis >=0, txt ~p)
__device__ __align__(16) __half g_xh[(size_t)(TOKENS + 128) * KDIM];
__device__ __align__(16) __half g_wh[(size_t)2 * NDIM * KDIM];

__global__ void init_kernel(const uint32_t* __restrict__ mask32) {
    if (threadIdx.x == 0) {
        int is_i32 = 1;
        #pragma unroll 8
        for (int i = 0; i < 64; i++)
            if (mask32[i] > 1u) { is_i32 = 0; break; }
        g_mask_is_i32 = is_i32;
        g_cnt[0] = 0;
        g_cnt[1] = 0;
    }
}

__global__ void build_lists_kernel(const void* __restrict__ mask) {
    int i = blockIdx.x * blockDim.x + threadIdx.x;
    if (i < TOKENS) {
        int m = g_mask_is_i32 ? ((const int*)mask)[i]
                              : (int)((const unsigned char*)mask)[i];
        if (m) { int p = atomicAdd(&g_cnt[0], 1); g_dst[i] = p; }
        else   { int p = atomicAdd(&g_cnt[1], 1); g_dst[i] = ~p; }
    }
}

// fp32 -> fp16 (rn) with k16-block permutation [2s,2s+1,2s+8,2s+9] -> [4s..4s+3]
__device__ __forceinline__ void cvt_permute8(const float4 v0, const float4 v1,
                                             __half out[8]) {
    out[0] = __float2half_rn(v0.x); out[1] = __float2half_rn(v0.y);
    out[2] = __float2half_rn(v1.x); out[3] = __float2half_rn(v1.y);
    out[4] = __float2half_rn(v0.z); out[5] = __float2half_rn(v0.w);
    out[6] = __float2half_rn(v1.z); out[7] = __float2half_rn(v1.w);
}

__global__ void __launch_bounds__(128) prep_x_kernel(const float* __restrict__ x) {
    const int tok = blockIdx.x;
    const int t = threadIdx.x;
    const int cv = g_cnt[0];
    const int d = g_dst[tok];
    const int row = (d >= 0) ? d : cv + ~d;
    if (t == 0) g_rows[row] = tok;
    const int blk = t >> 1, h = t & 1;
    const float* src = x + (size_t)tok * KDIM + blk * 16;
    const float4 v0 = *(const float4*)(src + 4 * h);
    const float4 v1 = *(const float4*)(src + 4 * h + 8);
    __half o[8];
    cvt_permute8(v0, v1, o);
    *(uint4*)(g_xh + (size_t)row * KDIM + blk * 16 + 8 * h) = *(const uint4*)o;
}

__global__ void __launch_bounds__(128) prep_w_kernel(const float* __restrict__ w_v,
                                                     const float* __restrict__ w_t) {
    const int r = blockIdx.x;                  // 0..2047
    const int t = threadIdx.x;
    const float* src_base = (r < NDIM) ? w_v : w_t;
    const int rr = (r < NDIM) ? r : r - NDIM;
    const int blk = t >> 1, h = t & 1;
    const float* src = src_base + (size_t)rr * KDIM + blk * 16;
    const float4 v0 = *(const float4*)(src + 4 * h);
    const float4 v1 = *(const float4*)(src + 4 * h + 8);
    __half o[8];
    cvt_permute8(v0, v1, o);
    *(uint4*)(g_wh + (size_t)r * KDIM + blk * 16 + 8 * h) = *(const uint4*)o;
}

__device__ __forceinline__ void cp_async16(uint32_t d, const void* s) {
    asm volatile("cp.async.cg.shared.global [%0], [%1], 16;" :: "r"(d), "l"(s));
}
#define CP_COMMIT() asm volatile("cp.async.commit_group;")

// ---------------------------------------------------------------------------
// Routed GEMM (fp16 MMA): grid = (8, 513); 256 threads, occ 2.
// 4-stage cp.async ring, ONE __syncthreads per k-iter, loads issued pre-compute.
// ---------------------------------------------------------------------------
__global__ void __launch_bounds__(256, 2) routed_gemm_kernel(float* __restrict__ out)
{
    extern __shared__ __half smem[];       // [STAGES][STAGE_H]
    __shared__ int rows_s[BM];

    const int cv = g_cnt[0];
    const int ct = g_cnt[1];
    const int vis_tiles = (cv + BM - 1) >> 7;

    const int tile = blockIdx.y;
    int row0, count_lim;
    const __half* W;
    if (tile < vis_tiles) {
        row0 = tile << 7;          count_lim = cv;       W = g_wh;
    } else {
        const int base = (tile - vis_tiles) << 7;
        if (base >= ct) return;
        row0 = cv + base;          count_lim = cv + ct;  W = g_wh + (size_t)NDIM * KDIM;
    }
    const int mvalid = min(BM, count_lim - row0);

    const int tid = threadIdx.x;
    if (tid < BM) rows_s[tid] = g_rows[min(row0 + tid, TOKENS - 1)];

    const int n_cta = blockIdx.x * BN;

    auto load_stage = [&](int kt) {
        const int s = kt & (STAGES - 1);
        const int k0 = kt * BK;                  // halves
        __half* Ab = smem + s * STAGE_H;
        __half* Bb = Ab + A_STRIDE;
        #pragma unroll
        for (int i = 0; i < 2; i++) {            // A: 512 x 16B chunks
            const int idx = i * 256 + tid;
            const int r = idx >> 2, cg = idx & 3;
            uint32_t d = (uint32_t)__cvta_generic_to_shared(&Ab[r * PAD_H + cg * 8]);
            cp_async16(d, g_xh + (size_t)(row0 + r) * KDIM + k0 + cg * 8);
        }
        #pragma unroll
        for (int i = 0; i < 2; i++) {            // B: 512 x 16B chunks
            const int idx = i * 256 + tid;
            const int r = idx >> 2, cg = idx & 3;
            uint32_t d = (uint32_t)__cvta_generic_to_shared(&Bb[r * PAD_H + cg * 8]);
            cp_async16(d, W + (size_t)(n_cta + r) * KDIM + k0 + cg * 8);
        }
        CP_COMMIT();
    };

    const int lane = tid & 31;
    const int g  = lane >> 2;
    const int tg = lane & 3;
    const int wid = tid >> 5;
    const int m0  = (wid >> 2) * 64;
    const int n0w = (wid & 3) * 32;

    float acc[4][4][4];
    #pragma unroll
    for (int mt = 0; mt < 4; mt++)
        #pragma unroll
        for (int nt = 0; nt < 4; nt++)
            #pragma unroll
            for (int r = 0; r < 4; r++) acc[mt][nt][r] = 0.0f;

    // prologue: 3 stages in flight (rows_s is written before any cp.async reads it:
    // A loads use row0+r directly; rows_s only used in epilogue — but keep barrier
    // for smem write visibility of rows_s before epilogue; the pipeline needs none)
    load_stage(0);
    load_stage(1);
    load_stage(2);

    for (int kt = 0; kt < NKITER; kt++) {
        asm volatile("cp.async.wait_group 2;");
        __syncthreads();                 // stage kt visible; slot (kt-1)%4 free

        if (kt + 3 < NKITER) load_stage(kt + 3);

        const int s = kt & (STAGES - 1);
        const __half* Ab = smem + s * STAGE_H;
        const __half* Bb = Ab + A_STRIDE;

        #pragma unroll
        for (int ks = 0; ks < 2; ks++) {
            const int co = ks * 16 + tg * 4;
            uint2 a_lo[4], a_hi[4], b[4];
            #pragma unroll
            for (int mt = 0; mt < 4; mt++) {
                const int r = m0 + mt * 16 + g;
                a_lo[mt] = *(const uint2*)&Ab[r * PAD_H + co];
                a_hi[mt] = *(const uint2*)&Ab[(r + 8) * PAD_H + co];
            }
            #pragma unroll
            for (int nt = 0; nt < 4; nt++) {
                const int n = n0w + nt * 8 + g;
                b[nt] = *(const uint2*)&Bb[n * PAD_H + co];
            }
            #pragma unroll
            for (int mt = 0; mt < 4; mt++)
                #pragma unroll
                for (int nt = 0; nt < 4; nt++)
                    asm volatile(
                        "mma.sync.aligned.m16n8k16.row.col.f32.f16.f16.f32 "
                        "{%0,%1,%2,%3}, {%4,%5,%6,%7}, {%8,%9}, {%0,%1,%2,%3};\n"
                        : "+f"(acc[mt][nt][0]), "+f"(acc[mt][nt][1]),
                          "+f"(acc[mt][nt][2]), "+f"(acc[mt][nt][3])
                        : "r"(a_lo[mt].x), "r"(a_hi[mt].x),
                          "r"(a_lo[mt].y), "r"(a_hi[mt].y),
                          "r"(b[nt].x),    "r"(b[nt].y));
        }
    }

    // ---- epilogue: scatter float2 per fragment row
    #pragma unroll
    for (int mt = 0; mt < 4; mt++) {
        const int r_lo = m0 + mt * 16 + g;
        const int r_hi = r_lo + 8;
        const bool ok_lo = r_lo < mvalid;
        const bool ok_hi = r_hi < mvalid;
        float* row_lo = ok_lo ? out + (size_t)rows_s[r_lo] * NDIM + n_cta : nullptr;
        float* row_hi = ok_hi ? out + (size_t)rows_s[r_hi] * NDIM + n_cta : nullptr;
        #pragma unroll
        for (int nt = 0; nt < 4; nt++) {
            const int col = n0w + nt * 8 + tg * 2;
            if (ok_lo)
                *(float2*)(row_lo + col) = make_float2(acc[mt][nt][0], acc[mt][nt][1]);
            if (ok_hi)
                *(float2*)(row_hi + col) = make_float2(acc[mt][nt][2], acc[mt][nt][3]);
        }
    }
}

// ---------------------------------------------------------------------------
// Launch (graph-capturable)
// ---------------------------------------------------------------------------
extern "C" void kernel_launch(void* const* d_in, const int* in_sizes, int n_in,
                              void* d_out, int out_size)
{
    const float* x    = (const float*)d_in[0];
    const void*  mask = d_in[1];
    const float* w_v  = (const float*)d_in[2];
    const float* w_t  = (const float*)d_in[3];
    float*       out  = (float*)d_out;

    init_kernel<<<1, 32>>>((const uint32_t*)mask);
    build_lists_kernel<<<TOKENS / 256, 256>>>(mask);
    prep_x_kernel<<<TOKENS, 128>>>(x);
    prep_w_kernel<<<2 * NDIM, 128>>>(w_v, w_t);

    const size_t smem_bytes = (size_t)STAGES * STAGE_H * sizeof(__half); // 81920
    cudaFuncSetAttribute(routed_gemm_kernel,
                         cudaFuncAttributeMaxDynamicSharedMemorySize,
                         (int)smem_bytes);

    dim3 grid(NDIM / BN, 513);
    routed_gemm_kernel<<<grid, 256, smem_bytes>>>(out);
}